// round 13
// baseline (speedup 1.0000x reference)
#include <cuda_runtime.h>

// Problem constants
#define NPTS        8192
#define BROWS       4096
#define KTOT        (NPTS * 3)            // 24576 floats per row
#define K4          (KTOT / 4)            // 6144 float4 per row

// Config: single fused kernel, 1 CTA/SM, NTILES=3 (best measured body).
#define GRID_MAIN    152
#define THREADS_MAIN 512
#define NWARPS       (THREADS_MAIN / 32)  // 16
#define NTILES       3
#define TILE_K4      (K4 / NTILES)        // 2048 float4 per tile
#define UNROLL       (TILE_K4 / THREADS_MAIN) // 4
#define MAX_LROWS    ((BROWS + GRID_MAIN - 1) / GRID_MAIN) // 27

__device__ __forceinline__ float softplus_fast(float x) {
    float e = __expf(-fabsf(x));
    return fmaxf(x, 0.0f) + __logf(1.0f + e);
}

struct Sym6 { float s00, s01, s02, s11, s12, s22; };

__device__ __forceinline__ Sym6 make_sym(const float* __restrict__ w) {
    float a = softplus_fast(w[0]);
    float b = w[1];
    float c = w[2];
    float d = softplus_fast(w[3]);
    float e = w[4];
    float f = softplus_fast(w[5]);
    Sym6 s;
    s.s00 = a * a;
    s.s01 = a * b;
    s.s02 = a * c;
    s.s11 = fmaf(b, b, d * d);
    s.s12 = fmaf(b, c, d * e);
    s.s22 = fmaf(c, c, fmaf(e, e, f * f));
    return s;
}

// ---------------------------------------------------------------------------
// Fused kernel: out[b,j] = sum_k x[b,k]*W[j][k] + NPTS*bias[j].
// Static row partition, register-resident W built inline per tile from
// `weight` (fast softplus), pair-0 x loads issued BEFORE the W build so
// setup hides under in-flight data, next-pair loads issued between the FMA
// block and the shuffle tree. Measured at the HBM streaming roofline
// (~6.2 TB/s, 78% of spec) for this read-once access pattern.
// ---------------------------------------------------------------------------
__global__ void __launch_bounds__(THREADS_MAIN, 1)
symm_fused_kernel(const float* __restrict__ x,
                  const float* __restrict__ weight,
                  const float* __restrict__ bias,
                  float* __restrict__ out) {
    __shared__ float part[MAX_LROWS][NWARPS][3];

    const int tid  = threadIdx.x;
    const int wid  = tid >> 5;
    const int lane = tid & 31;
    const int bid  = blockIdx.x;

    const float4* __restrict__ x4 = reinterpret_cast<const float4*>(x);

    const int nrows  = (BROWS - 1 - bid) / GRID_MAIN + 1;   // 26 or 27
    const int npairs = (nrows + 1) / 2;

    for (int tile = 0; tile < NTILES; ++tile) {
        const int base4 = tile * TILE_K4;

        // ---- Issue pair-0's 8 independent LDG.128 FIRST. ----
        float4 xv0[UNROLL], xv1[UNROLL];
        {
            const int r0 = bid;
            const int r1 = (r0 + GRID_MAIN < BROWS) ? r0 + GRID_MAIN : r0;
            const float4* __restrict__ xr0 = x4 + (size_t)r0 * K4 + base4;
            const float4* __restrict__ xr1 = x4 + (size_t)r1 * K4 + base4;
#pragma unroll
            for (int i = 0; i < UNROLL; ++i) {
                xv0[i] = __ldcs(&xr0[i * THREADS_MAIN + tid]);
                xv1[i] = __ldcs(&xr1[i * THREADS_MAIN + tid]);
            }
        }

        // ---- Build register-resident W slice (hides under the loads). ----
        float4 w0r[UNROLL], w1r[UNROLL], w2r[UNROLL];
#pragma unroll
        for (int i = 0; i < UNROLL; ++i) {
            const int idx = base4 + i * THREADS_MAIN + tid;
            const int k0  = 4 * idx;
            const int n0  = k0 / 3;
            const int phi = k0 - 3 * n0;

            Sym6 S0 = make_sym(weight + (size_t)n0 * 6);
            Sym6 S1 = make_sym(weight + (size_t)(n0 + 1) * 6);

            if (phi == 0) {
                w0r[i] = make_float4(S0.s00, S0.s01, S0.s02, S1.s00);
                w1r[i] = make_float4(S0.s01, S0.s11, S0.s12, S1.s01);
                w2r[i] = make_float4(S0.s02, S0.s12, S0.s22, S1.s02);
            } else if (phi == 1) {
                w0r[i] = make_float4(S0.s01, S0.s02, S1.s00, S1.s01);
                w1r[i] = make_float4(S0.s11, S0.s12, S1.s01, S1.s11);
                w2r[i] = make_float4(S0.s12, S0.s22, S1.s02, S1.s12);
            } else {
                w0r[i] = make_float4(S0.s02, S1.s00, S1.s01, S1.s02);
                w1r[i] = make_float4(S0.s12, S1.s01, S1.s11, S1.s12);
                w2r[i] = make_float4(S0.s22, S1.s02, S1.s12, S1.s22);
            }
        }

        // ---- Row-pair loop (R=2), single buffer, prefetch-after-FMA. ----
        for (int p = 0; p < npairs; ++p) {
            const int  r1     = bid + (2 * p + 1) * GRID_MAIN;
            const bool has_r1 = (r1 < BROWS);

            float a0 = 0.0f, a1 = 0.0f, a2 = 0.0f;
            float b0 = 0.0f, b1 = 0.0f, b2 = 0.0f;
#pragma unroll
            for (int i = 0; i < UNROLL; ++i) {
                a0 = fmaf(xv0[i].x, w0r[i].x, a0); a0 = fmaf(xv0[i].y, w0r[i].y, a0);
                a0 = fmaf(xv0[i].z, w0r[i].z, a0); a0 = fmaf(xv0[i].w, w0r[i].w, a0);
                a1 = fmaf(xv0[i].x, w1r[i].x, a1); a1 = fmaf(xv0[i].y, w1r[i].y, a1);
                a1 = fmaf(xv0[i].z, w1r[i].z, a1); a1 = fmaf(xv0[i].w, w1r[i].w, a1);
                a2 = fmaf(xv0[i].x, w2r[i].x, a2); a2 = fmaf(xv0[i].y, w2r[i].y, a2);
                a2 = fmaf(xv0[i].z, w2r[i].z, a2); a2 = fmaf(xv0[i].w, w2r[i].w, a2);

                b0 = fmaf(xv1[i].x, w0r[i].x, b0); b0 = fmaf(xv1[i].y, w0r[i].y, b0);
                b0 = fmaf(xv1[i].z, w0r[i].z, b0); b0 = fmaf(xv1[i].w, w0r[i].w, b0);
                b1 = fmaf(xv1[i].x, w1r[i].x, b1); b1 = fmaf(xv1[i].y, w1r[i].y, b1);
                b1 = fmaf(xv1[i].z, w1r[i].z, b1); b1 = fmaf(xv1[i].w, w1r[i].w, b1);
                b2 = fmaf(xv1[i].x, w2r[i].x, b2); b2 = fmaf(xv1[i].y, w2r[i].y, b2);
                b2 = fmaf(xv1[i].z, w2r[i].z, b2); b2 = fmaf(xv1[i].w, w2r[i].w, b2);
            }

            // Prefetch next pair NOW (accumulators done with xv); the loads
            // fly while we run the shuffle tree and partial store.
            if (p + 1 < npairs) {
                int nr0 = bid + (2 * (p + 1)) * GRID_MAIN;
                int nr1 = nr0 + GRID_MAIN;
                if (nr1 >= BROWS) nr1 = nr0;
                const float4* __restrict__ xr0 = x4 + (size_t)nr0 * K4 + base4;
                const float4* __restrict__ xr1 = x4 + (size_t)nr1 * K4 + base4;
#pragma unroll
                for (int i = 0; i < UNROLL; ++i) {
                    xv0[i] = __ldcs(&xr0[i * THREADS_MAIN + tid]);
                    xv1[i] = __ldcs(&xr1[i * THREADS_MAIN + tid]);
                }
            }

#pragma unroll
            for (int off = 16; off > 0; off >>= 1) {
                a0 += __shfl_xor_sync(0xffffffffu, a0, off);
                b0 += __shfl_xor_sync(0xffffffffu, b0, off);
                a1 += __shfl_xor_sync(0xffffffffu, a1, off);
                b1 += __shfl_xor_sync(0xffffffffu, b1, off);
                a2 += __shfl_xor_sync(0xffffffffu, a2, off);
                b2 += __shfl_xor_sync(0xffffffffu, b2, off);
            }

            if (lane == 0) {
                const int lr0 = 2 * p;
                if (tile == 0) {
                    part[lr0][wid][0] = a0;
                    part[lr0][wid][1] = a1;
                    part[lr0][wid][2] = a2;
                    if (has_r1) {
                        part[lr0 + 1][wid][0] = b0;
                        part[lr0 + 1][wid][1] = b1;
                        part[lr0 + 1][wid][2] = b2;
                    }
                } else {
                    part[lr0][wid][0] += a0;
                    part[lr0][wid][1] += a1;
                    part[lr0][wid][2] += a2;
                    if (has_r1) {
                        part[lr0 + 1][wid][0] += b0;
                        part[lr0 + 1][wid][1] += b1;
                        part[lr0 + 1][wid][2] += b2;
                    }
                }
            }
        }
    }

    __syncthreads();

    // Final cross-warp reduction + bias.
    for (int o = tid; o < nrows * 3; o += THREADS_MAIN) {
        int lr = o / 3;
        int j  = o - lr * 3;
        float s = 0.0f;
#pragma unroll
        for (int w = 0; w < NWARPS; ++w) s += part[lr][w][j];
        int row = bid + lr * GRID_MAIN;
        out[row * 3 + j] = s + (float)NPTS * __ldg(&bias[j]);
    }
}

// ---------------------------------------------------------------------------
extern "C" void kernel_launch(void* const* d_in, const int* in_sizes, int n_in,
                              void* d_out, int out_size) {
    const float* x      = (const float*)d_in[0];
    const float* weight = (const float*)d_in[1];
    const float* bias   = (const float*)d_in[2];
    float*       out    = (float*)d_out;
    (void)in_sizes; (void)n_in; (void)out_size;

    symm_fused_kernel<<<GRID_MAIN, THREADS_MAIN>>>(x, weight, bias, out);
}

// round 14
// speedup vs baseline: 1.0107x; 1.0107x over previous
#include <cuda_runtime.h>

// Problem constants
#define NPTS        8192
#define BROWS       4096
#define KTOT        (NPTS * 3)            // 24576 floats per row
#define K4          (KTOT / 4)            // 6144 float4 per row

// Config: single fused kernel, 1 CTA/SM, NTILES=3 (champion body),
// CONTIGUOUS row chunks per block for DRAM page locality.
#define GRID_MAIN    152
#define THREADS_MAIN 512
#define NWARPS       (THREADS_MAIN / 32)  // 16
#define NTILES       3
#define TILE_K4      (K4 / NTILES)        // 2048 float4 per tile
#define UNROLL       (TILE_K4 / THREADS_MAIN) // 4
#define MAX_LROWS    27                   // 4096 = 144*27 + 8*26
#define ROWS_BASE    26
#define REM_BLOCKS   144                  // blocks 0..143 get 27 rows

__device__ __forceinline__ float softplus_fast(float x) {
    float e = __expf(-fabsf(x));
    return fmaxf(x, 0.0f) + __logf(1.0f + e);
}

struct Sym6 { float s00, s01, s02, s11, s12, s22; };

__device__ __forceinline__ Sym6 make_sym(const float* __restrict__ w) {
    float a = softplus_fast(w[0]);
    float b = w[1];
    float c = w[2];
    float d = softplus_fast(w[3]);
    float e = w[4];
    float f = softplus_fast(w[5]);
    Sym6 s;
    s.s00 = a * a;
    s.s01 = a * b;
    s.s02 = a * c;
    s.s11 = fmaf(b, b, d * d);
    s.s12 = fmaf(b, c, d * e);
    s.s22 = fmaf(c, c, fmaf(e, e, f * f));
    return s;
}

// ---------------------------------------------------------------------------
// Fused kernel, champion body with contiguous row chunks:
// block bid owns rows [start, start+nrows), processed as adjacent pairs
// (r, r+1) — each CTA streams one long sequential region per tile.
// ---------------------------------------------------------------------------
__global__ void __launch_bounds__(THREADS_MAIN, 1)
symm_fused_kernel(const float* __restrict__ x,
                  const float* __restrict__ weight,
                  const float* __restrict__ bias,
                  float* __restrict__ out) {
    __shared__ float part[MAX_LROWS][NWARPS][3];

    const int tid  = threadIdx.x;
    const int wid  = tid >> 5;
    const int lane = tid & 31;
    const int bid  = blockIdx.x;

    const float4* __restrict__ x4 = reinterpret_cast<const float4*>(x);

    const int start  = bid * ROWS_BASE + (bid < REM_BLOCKS ? bid : REM_BLOCKS);
    const int nrows  = ROWS_BASE + (bid < REM_BLOCKS ? 1 : 0);   // 26 or 27
    const int npairs = (nrows + 1) / 2;

    for (int tile = 0; tile < NTILES; ++tile) {
        const int base4 = tile * TILE_K4;

        // ---- Issue pair-0's 8 independent LDG.128 FIRST. ----
        float4 xv0[UNROLL], xv1[UNROLL];
        {
            const int r0 = start;
            const int r1 = (1 < nrows) ? r0 + 1 : r0;
            const float4* __restrict__ xr0 = x4 + (size_t)r0 * K4 + base4;
            const float4* __restrict__ xr1 = x4 + (size_t)r1 * K4 + base4;
#pragma unroll
            for (int i = 0; i < UNROLL; ++i) {
                xv0[i] = __ldcs(&xr0[i * THREADS_MAIN + tid]);
                xv1[i] = __ldcs(&xr1[i * THREADS_MAIN + tid]);
            }
        }

        // ---- Build register-resident W slice (hides under the loads). ----
        float4 w0r[UNROLL], w1r[UNROLL], w2r[UNROLL];
#pragma unroll
        for (int i = 0; i < UNROLL; ++i) {
            const int idx = base4 + i * THREADS_MAIN + tid;
            const int k0  = 4 * idx;
            const int n0  = k0 / 3;
            const int phi = k0 - 3 * n0;

            Sym6 S0 = make_sym(weight + (size_t)n0 * 6);
            Sym6 S1 = make_sym(weight + (size_t)(n0 + 1) * 6);

            if (phi == 0) {
                w0r[i] = make_float4(S0.s00, S0.s01, S0.s02, S1.s00);
                w1r[i] = make_float4(S0.s01, S0.s11, S0.s12, S1.s01);
                w2r[i] = make_float4(S0.s02, S0.s12, S0.s22, S1.s02);
            } else if (phi == 1) {
                w0r[i] = make_float4(S0.s01, S0.s02, S1.s00, S1.s01);
                w1r[i] = make_float4(S0.s11, S0.s12, S1.s01, S1.s11);
                w2r[i] = make_float4(S0.s12, S0.s22, S1.s02, S1.s12);
            } else {
                w0r[i] = make_float4(S0.s02, S1.s00, S1.s01, S1.s02);
                w1r[i] = make_float4(S0.s12, S1.s01, S1.s11, S1.s12);
                w2r[i] = make_float4(S0.s22, S1.s02, S1.s12, S1.s22);
            }
        }

        // ---- Row-pair loop: adjacent rows (start+2p, start+2p+1). ----
        for (int p = 0; p < npairs; ++p) {
            const bool has_r1 = (2 * p + 1 < nrows);

            float a0 = 0.0f, a1 = 0.0f, a2 = 0.0f;
            float b0 = 0.0f, b1 = 0.0f, b2 = 0.0f;
#pragma unroll
            for (int i = 0; i < UNROLL; ++i) {
                a0 = fmaf(xv0[i].x, w0r[i].x, a0); a0 = fmaf(xv0[i].y, w0r[i].y, a0);
                a0 = fmaf(xv0[i].z, w0r[i].z, a0); a0 = fmaf(xv0[i].w, w0r[i].w, a0);
                a1 = fmaf(xv0[i].x, w1r[i].x, a1); a1 = fmaf(xv0[i].y, w1r[i].y, a1);
                a1 = fmaf(xv0[i].z, w1r[i].z, a1); a1 = fmaf(xv0[i].w, w1r[i].w, a1);
                a2 = fmaf(xv0[i].x, w2r[i].x, a2); a2 = fmaf(xv0[i].y, w2r[i].y, a2);
                a2 = fmaf(xv0[i].z, w2r[i].z, a2); a2 = fmaf(xv0[i].w, w2r[i].w, a2);

                b0 = fmaf(xv1[i].x, w0r[i].x, b0); b0 = fmaf(xv1[i].y, w0r[i].y, b0);
                b0 = fmaf(xv1[i].z, w0r[i].z, b0); b0 = fmaf(xv1[i].w, w0r[i].w, b0);
                b1 = fmaf(xv1[i].x, w1r[i].x, b1); b1 = fmaf(xv1[i].y, w1r[i].y, b1);
                b1 = fmaf(xv1[i].z, w1r[i].z, b1); b1 = fmaf(xv1[i].w, w1r[i].w, b1);
                b2 = fmaf(xv1[i].x, w2r[i].x, b2); b2 = fmaf(xv1[i].y, w2r[i].y, b2);
                b2 = fmaf(xv1[i].z, w2r[i].z, b2); b2 = fmaf(xv1[i].w, w2r[i].w, b2);
            }

            // Prefetch next adjacent pair NOW; loads fly during the
            // shuffle tree and partial store.
            if (p + 1 < npairs) {
                int nr0 = start + 2 * (p + 1);
                int nr1 = (2 * (p + 1) + 1 < nrows) ? nr0 + 1 : nr0;
                const float4* __restrict__ xr0 = x4 + (size_t)nr0 * K4 + base4;
                const float4* __restrict__ xr1 = x4 + (size_t)nr1 * K4 + base4;
#pragma unroll
                for (int i = 0; i < UNROLL; ++i) {
                    xv0[i] = __ldcs(&xr0[i * THREADS_MAIN + tid]);
                    xv1[i] = __ldcs(&xr1[i * THREADS_MAIN + tid]);
                }
            }

#pragma unroll
            for (int off = 16; off > 0; off >>= 1) {
                a0 += __shfl_xor_sync(0xffffffffu, a0, off);
                b0 += __shfl_xor_sync(0xffffffffu, b0, off);
                a1 += __shfl_xor_sync(0xffffffffu, a1, off);
                b1 += __shfl_xor_sync(0xffffffffu, b1, off);
                a2 += __shfl_xor_sync(0xffffffffu, a2, off);
                b2 += __shfl_xor_sync(0xffffffffu, b2, off);
            }

            if (lane == 0) {
                const int lr0 = 2 * p;
                if (tile == 0) {
                    part[lr0][wid][0] = a0;
                    part[lr0][wid][1] = a1;
                    part[lr0][wid][2] = a2;
                    if (has_r1) {
                        part[lr0 + 1][wid][0] = b0;
                        part[lr0 + 1][wid][1] = b1;
                        part[lr0 + 1][wid][2] = b2;
                    }
                } else {
                    part[lr0][wid][0] += a0;
                    part[lr0][wid][1] += a1;
                    part[lr0][wid][2] += a2;
                    if (has_r1) {
                        part[lr0 + 1][wid][0] += b0;
                        part[lr0 + 1][wid][1] += b1;
                        part[lr0 + 1][wid][2] += b2;
                    }
                }
            }
        }
    }

    __syncthreads();

    // Final cross-warp reduction + bias (contiguous output rows).
    for (int o = tid; o < nrows * 3; o += THREADS_MAIN) {
        int lr = o / 3;
        int j  = o - lr * 3;
        float s = 0.0f;
#pragma unroll
        for (int w = 0; w < NWARPS; ++w) s += part[lr][w][j];
        int row = start + lr;
        out[row * 3 + j] = s + (float)NPTS * __ldg(&bias[j]);
    }
}

// ---------------------------------------------------------------------------
extern "C" void kernel_launch(void* const* d_in, const int* in_sizes, int n_in,
                              void* d_out, int out_size) {
    const float* x      = (const float*)d_in[0];
    const float* weight = (const float*)d_in[1];
    const float* bias   = (const float*)d_in[2];
    float*       out    = (float*)d_out;
    (void)in_sizes; (void)n_in; (void)out_size;

    symm_fused_kernel<<<GRID_MAIN, THREADS_MAIN>>>(x, weight, bias, out);
}